// round 5
// baseline (speedup 1.0000x reference)
#include <cuda_runtime.h>
#include <cuda_bf16.h>
#include <math.h>

#define NMAX 100000
#define EMAX 1000000
#define HID 128

// ---------------- scratch (device globals; no runtime allocation) ------------
__device__ __align__(16) int   g_cnt[NMAX];
__device__ __align__(16) int   g_off[NMAX + 1];
__device__ __align__(16) int   g_cur[NMAX];
__device__ __align__(16) float g_dinv[NMAX];
__device__ __align__(16) int   g_col[EMAX];
__device__ __align__(16) float g_w[EMAX];
__device__ __align__(16) float g_buf1[(size_t)NMAX * HID];
__device__ __align__(16) float g_buf2[(size_t)NMAX * HID];
__device__ __align__(16) int   g_bsums[64];
__device__ int g_is64;

static inline int ceil_div(int a, int b) { return (a + b - 1) / b; }

// index loader that works for int32 or int64 edge_index
__device__ __forceinline__ int load_idx(const void* p, int is64, long long i) {
    if (is64) return (int)((const long long*)p)[i];
    return ((const int*)p)[i];
}

// ---------------- dtype detection --------------------------------------------
// If edge_index is int64 (values < 2^31), every odd 32-bit word of the first
// 1024 pairs is 0. Genuine random int32 node ids make that essentially
// impossible, so "all odd words zero" <=> int64.
__global__ void k_detect(const int* __restrict__ p, int nwords) {
    bool oddzero = true;
    for (int i = threadIdx.x; i < 1024; i += 32) {
        int w = 2 * i + 1;
        if (w < nwords && p[w] != 0) oddzero = false;
    }
    oddzero = __all_sync(0xffffffffu, oddzero);
    if (threadIdx.x == 0) g_is64 = oddzero ? 1 : 0;
}

// ---------------- preprocessing ----------------------------------------------
__global__ void k_zero_cnt(int n) {
    int i = blockIdx.x * blockDim.x + threadIdx.x;
    if (i < n) g_cnt[i] = 0;
}

__global__ void k_hist(const void* __restrict__ ei, int ne, int n) {
    int e = blockIdx.x * blockDim.x + threadIdx.x;
    int is64 = g_is64;
    if (e < ne) {
        int d = load_idx(ei, is64, (long long)ne + e);  // dst row
        if (d >= 0 && d < n) atomicAdd(&g_cnt[d], 1);
    }
}

// block of 256 threads scans 2048 counts (8 per thread)
__global__ void k_scan1(int n) {
    __shared__ int sh[256];
    int tid  = threadIdx.x;
    int base = blockIdx.x * 2048;
    int vals[8];
    int tsum = 0;
#pragma unroll
    for (int v = 0; v < 8; v++) {
        int idx = base + tid * 8 + v;
        vals[v] = (idx < n) ? g_cnt[idx] : 0;
        tsum += vals[v];
    }
    sh[tid] = tsum;
    __syncthreads();
    for (int s = 1; s < 256; s <<= 1) {
        int t = (tid >= s) ? sh[tid - s] : 0;
        __syncthreads();
        sh[tid] += t;
        __syncthreads();
    }
    int run = sh[tid] - tsum;  // exclusive prefix within block
    if (tid == 255) g_bsums[blockIdx.x] = sh[255];
#pragma unroll
    for (int v = 0; v < 8; v++) {
        int idx = base + tid * 8 + v;
        if (idx < n) g_off[idx] = run;
        run += vals[v];
    }
}

__global__ void k_scan2(int nb) {
    if (threadIdx.x == 0 && blockIdx.x == 0) {
        int run = 0;
        for (int b = 0; b < nb; b++) {
            int t = g_bsums[b];
            g_bsums[b] = run;
            run += t;
        }
    }
}

__global__ void k_scan3(int n, int ne) {
    int i = blockIdx.x * blockDim.x + threadIdx.x;
    if (i < n) {
        int o = g_off[i] + g_bsums[i >> 11];
        g_off[i] = o;
        g_cur[i] = o;
        g_dinv[i] = rsqrtf((float)(g_cnt[i] + 1));  // +1 self loop
        if (i == 0) g_off[n] = ne;
    }
}

__global__ void k_fill(const void* __restrict__ ei, int ne, int n) {
    int e = blockIdx.x * blockDim.x + threadIdx.x;
    int is64 = g_is64;
    if (e < ne) {
        int s = load_idx(ei, is64, e);
        int d = load_idx(ei, is64, (long long)ne + e);
        if (s >= 0 && s < n && d >= 0 && d < n) {
            int p = atomicAdd(&g_cur[d], 1);
            g_col[p] = s;
            g_w[p]   = g_dinv[s] * g_dinv[d];
        }
    }
}

// ---------------- GEMM: O[n,128] = X[n,K] @ W[K,128] -------------------------
// 256 threads = 8 warps; each warp computes 8 rows; lane covers cols 4*lane..+3.
// K processed in chunks of 64 so smem stays at 48KB STATIC.
template <int K, int SRC, int DST>
__global__ void k_gemm(const float* __restrict__ Xext, const float* __restrict__ W, int n) {
    __shared__ __align__(16) float Ws[64 * 128];    // 32KB
    __shared__ __align__(16) float Xs[8 * 8 * 64];  // 16KB
    const float* X = (SRC == 0) ? Xext : (SRC == 1 ? g_buf1 : g_buf2);
    float* O = (DST == 1) ? g_buf1 : g_buf2;

    int tid = threadIdx.x, lane = tid & 31, warp = tid >> 5;
    float* myX = Xs + warp * (8 * 64);
    int rowbase = blockIdx.x * 64 + warp * 8;

    float4 acc[8];
#pragma unroll
    for (int r = 0; r < 8; r++) acc[r] = make_float4(0.f, 0.f, 0.f, 0.f);

    for (int c = 0; c < K; c += 64) {
        __syncthreads();
        for (int i = tid; i < 64 * 128; i += 256) Ws[i] = W[c * 128 + i];
#pragma unroll
        for (int r = 0; r < 8; r++) {
            int row = rowbase + r;
            const float* xr = X + (size_t)row * K + c;
            myX[r * 64 + lane]      = (row < n) ? xr[lane]      : 0.f;
            myX[r * 64 + lane + 32] = (row < n) ? xr[lane + 32] : 0.f;
        }
        __syncthreads();

        const float4* Ws4  = (const float4*)Ws;
        const float4* myX4 = (const float4*)myX;
#pragma unroll 4
        for (int k0 = 0; k0 < 64; k0 += 4) {
            float4 w0 = Ws4[(k0 + 0) * 32 + lane];
            float4 w1 = Ws4[(k0 + 1) * 32 + lane];
            float4 w2 = Ws4[(k0 + 2) * 32 + lane];
            float4 w3 = Ws4[(k0 + 3) * 32 + lane];
#pragma unroll
            for (int r = 0; r < 8; r++) {
                float4 xv = myX4[(r * 64 + k0) >> 2];
                acc[r].x = fmaf(xv.w, w3.x, fmaf(xv.z, w2.x, fmaf(xv.y, w1.x, fmaf(xv.x, w0.x, acc[r].x))));
                acc[r].y = fmaf(xv.w, w3.y, fmaf(xv.z, w2.y, fmaf(xv.y, w1.y, fmaf(xv.x, w0.y, acc[r].y))));
                acc[r].z = fmaf(xv.w, w3.z, fmaf(xv.z, w2.z, fmaf(xv.y, w1.z, fmaf(xv.x, w0.z, acc[r].z))));
                acc[r].w = fmaf(xv.w, w3.w, fmaf(xv.z, w2.w, fmaf(xv.y, w1.w, fmaf(xv.x, w0.w, acc[r].w))));
            }
        }
    }
#pragma unroll
    for (int r = 0; r < 8; r++) {
        int row = rowbase + r;
        if (row < n) ((float4*)(O + (size_t)row * HID))[lane] = acc[r];
    }
}

// ---------------- aggregation: Hout = relu(A_norm @ Hin + b) -----------------
template <int SRC, int DST>
__global__ void k_agg(const float* __restrict__ bias, int n) {
    const float* Hin = (SRC == 1) ? g_buf1 : g_buf2;
    float* Hout      = (DST == 1) ? g_buf1 : g_buf2;
    int lane = threadIdx.x & 31, warp = threadIdx.x >> 5;
    int i = blockIdx.x * 8 + warp;
    if (i >= n) return;
    int e0 = g_off[i], e1 = g_off[i + 1];
    float4 acc = make_float4(0.f, 0.f, 0.f, 0.f);
    for (int e = e0; e < e1; e++) {
        int s = g_col[e];
        float wv = g_w[e];
        float4 hv = ((const float4*)(Hin + (size_t)s * HID))[lane];
        acc.x = fmaf(wv, hv.x, acc.x);
        acc.y = fmaf(wv, hv.y, acc.y);
        acc.z = fmaf(wv, hv.z, acc.z);
        acc.w = fmaf(wv, hv.w, acc.w);
    }
    float di = g_dinv[i];
    float sw = di * di;  // self-loop weight
    float4 hs = ((const float4*)(Hin + (size_t)i * HID))[lane];
    float4 bv = ((const float4*)bias)[lane];
    acc.x = fmaxf(fmaf(sw, hs.x, acc.x) + bv.x, 0.f);
    acc.y = fmaxf(fmaf(sw, hs.y, acc.y) + bv.y, 0.f);
    acc.z = fmaxf(fmaf(sw, hs.z, acc.z) + bv.z, 0.f);
    acc.w = fmaxf(fmaf(sw, hs.w, acc.w) + bv.w, 0.f);
    ((float4*)(Hout + (size_t)i * HID))[lane] = acc;
}

// ---------------- head: out = log_softmax(H @ Wl + bl) -----------------------
__global__ void k_final(const float* __restrict__ Wl, const float* __restrict__ bl,
                        float* __restrict__ out, int n) {
    __shared__ __align__(16) float Wt[10 * 128];  // transposed: [j][k]
    __shared__ float bls[10];
    int tid = threadIdx.x;
    for (int idx = tid; idx < 1280; idx += 256) {
        int k = idx / 10, j = idx - 10 * k;
        Wt[j * 128 + k] = Wl[idx];
    }
    if (tid < 10) bls[tid] = bl[tid];
    __syncthreads();

    int lane = tid & 31, warp = tid >> 5;
    int i = blockIdx.x * 8 + warp;
    if (i >= n) return;
    float4 hv = ((const float4*)(g_buf2 + (size_t)i * HID))[lane];
    float lg[10];
#pragma unroll
    for (int j = 0; j < 10; j++) {
        float4 wv = ((const float4*)(Wt + j * 128))[lane];
        float p = hv.x * wv.x + hv.y * wv.y + hv.z * wv.z + hv.w * wv.w;
#pragma unroll
        for (int o = 16; o; o >>= 1) p += __shfl_xor_sync(0xffffffffu, p, o);
        lg[j] = p + bls[j];
    }
    float m = lg[0];
#pragma unroll
    for (int j = 1; j < 10; j++) m = fmaxf(m, lg[j]);
    float s = 0.f;
#pragma unroll
    for (int j = 0; j < 10; j++) s += expf(lg[j] - m);
    float lse = m + logf(s);
    if (lane < 10) out[(size_t)i * 10 + lane] = lg[lane] - lse;
}

// ---------------- launch -----------------------------------------------------
extern "C" void kernel_launch(void* const* d_in, const int* in_sizes, int n_in,
                              void* d_out, int out_size) {
    const float* x  = (const float*)d_in[0];
    const void*  ei = d_in[1];
    const float* W1 = (const float*)d_in[2];
    const float* b1 = (const float*)d_in[3];
    const float* W2 = (const float*)d_in[4];
    const float* b2 = (const float*)d_in[5];
    const float* Wl = (const float*)d_in[6];
    const float* bl = (const float*)d_in[7];
    float* out = (float*)d_out;

    int N = in_sizes[0] / 64;
    int E = in_sizes[1] / 2;  // element count: same for int32 or int64

    // --- detect edge_index dtype, then build normalized CSR ---
    k_detect<<<1, 32>>>((const int*)ei, 2 * E >= 2048 ? 2048 : 2 * E);
    k_zero_cnt<<<ceil_div(N, 256), 256>>>(N);
    k_hist<<<ceil_div(E, 256), 256>>>(ei, E, N);
    int nb = ceil_div(N, 2048);
    k_scan1<<<nb, 256>>>(N);
    k_scan2<<<1, 32>>>(nb);
    k_scan3<<<ceil_div(N, 256), 256>>>(N, E);
    k_fill<<<ceil_div(E, 256), 256>>>(ei, E, N);

    // --- layer 1: x @ W1 -> buf1; aggregate+relu -> buf2 ---
    k_gemm<64, 0, 1><<<ceil_div(N, 64), 256>>>(x, W1, N);
    k_agg<1, 2><<<ceil_div(N, 8), 256>>>(b1, N);

    // --- layer 2: buf2 @ W2 -> buf1; aggregate+relu -> buf2 ---
    k_gemm<128, 2, 1><<<ceil_div(N, 64), 256>>>(x, W2, N);
    k_agg<1, 2><<<ceil_div(N, 8), 256>>>(b2, N);

    // --- head + log_softmax ---
    k_final<<<ceil_div(N, 8), 256>>>(Wl, bl, out, N);
}

// round 6
// speedup vs baseline: 1.0418x; 1.0418x over previous
#include <cuda_runtime.h>
#include <cuda_bf16.h>
#include <math.h>

#define NMAX 100000
#define EMAX 1000000
#define HID 128

// ---------------- scratch (device globals; no runtime allocation) ------------
__device__ __align__(16) int   g_cnt[NMAX];
__device__ __align__(16) int   g_off[NMAX + 1];
__device__ __align__(16) int   g_cur[NMAX];
__device__ __align__(16) float g_dinv[NMAX];
__device__ __align__(16) int   g_col[EMAX];
__device__ __align__(16) float g_w[EMAX];
__device__ __align__(16) float g_buf1[(size_t)NMAX * HID];
__device__ __align__(16) float g_buf2[(size_t)NMAX * HID];
__device__ __align__(16) int   g_bsums[64];
__device__ int g_is64;

static inline int ceil_div(int a, int b) { return (a + b - 1) / b; }

// ---------------- f32x2 packed math helpers ----------------------------------
__device__ __forceinline__ unsigned long long ffma2(unsigned long long a,
                                                    unsigned long long b,
                                                    unsigned long long c) {
    unsigned long long d;
    asm("fma.rn.f32x2 %0, %1, %2, %3;" : "=l"(d) : "l"(a), "l"(b), "l"(c));
    return d;
}
__device__ __forceinline__ unsigned long long pack2(float lo, float hi) {
    unsigned long long d;
    asm("mov.b64 %0, {%1, %2};" : "=l"(d) : "r"(__float_as_uint(lo)), "r"(__float_as_uint(hi)));
    return d;
}
__device__ __forceinline__ float2 unpack2(unsigned long long v) {
    unsigned int lo, hi;
    asm("mov.b64 {%0, %1}, %2;" : "=r"(lo), "=r"(hi) : "l"(v));
    return make_float2(__uint_as_float(lo), __uint_as_float(hi));
}

// index loader that works for int32 or int64 edge_index
__device__ __forceinline__ int load_idx(const void* p, int is64, long long i) {
    if (is64) return (int)((const long long*)p)[i];
    return ((const int*)p)[i];
}

// ---------------- dtype detection --------------------------------------------
__global__ void k_detect(const int* __restrict__ p, int nwords) {
    bool oddzero = true;
    for (int i = threadIdx.x; i < 1024; i += 32) {
        int w = 2 * i + 1;
        if (w < nwords && p[w] != 0) oddzero = false;
    }
    oddzero = __all_sync(0xffffffffu, oddzero);
    if (threadIdx.x == 0) g_is64 = oddzero ? 1 : 0;
}

// ---------------- preprocessing ----------------------------------------------
__global__ void k_zero_cnt(int n) {
    int i = blockIdx.x * blockDim.x + threadIdx.x;
    if (i < n) g_cnt[i] = 0;
}

__global__ void k_hist(const void* __restrict__ ei, int ne, int n) {
    int e = blockIdx.x * blockDim.x + threadIdx.x;
    int is64 = g_is64;
    if (e < ne) {
        int d = load_idx(ei, is64, (long long)ne + e);
        if (d >= 0 && d < n) atomicAdd(&g_cnt[d], 1);
    }
}

__global__ void k_scan1(int n) {
    __shared__ int sh[256];
    int tid  = threadIdx.x;
    int base = blockIdx.x * 2048;
    int vals[8];
    int tsum = 0;
#pragma unroll
    for (int v = 0; v < 8; v++) {
        int idx = base + tid * 8 + v;
        vals[v] = (idx < n) ? g_cnt[idx] : 0;
        tsum += vals[v];
    }
    sh[tid] = tsum;
    __syncthreads();
    for (int s = 1; s < 256; s <<= 1) {
        int t = (tid >= s) ? sh[tid - s] : 0;
        __syncthreads();
        sh[tid] += t;
        __syncthreads();
    }
    int run = sh[tid] - tsum;
    if (tid == 255) g_bsums[blockIdx.x] = sh[255];
#pragma unroll
    for (int v = 0; v < 8; v++) {
        int idx = base + tid * 8 + v;
        if (idx < n) g_off[idx] = run;
        run += vals[v];
    }
}

__global__ void k_scan2(int nb) {
    if (threadIdx.x == 0 && blockIdx.x == 0) {
        int run = 0;
        for (int b = 0; b < nb; b++) {
            int t = g_bsums[b];
            g_bsums[b] = run;
            run += t;
        }
    }
}

__global__ void k_scan3(int n, int ne) {
    int i = blockIdx.x * blockDim.x + threadIdx.x;
    if (i < n) {
        int o = g_off[i] + g_bsums[i >> 11];
        g_off[i] = o;
        g_cur[i] = o;
        g_dinv[i] = rsqrtf((float)(g_cnt[i] + 1));  // +1 self loop
        if (i == 0) g_off[n] = ne;
    }
}

__global__ void k_fill(const void* __restrict__ ei, int ne, int n) {
    int e = blockIdx.x * blockDim.x + threadIdx.x;
    int is64 = g_is64;
    if (e < ne) {
        int s = load_idx(ei, is64, e);
        int d = load_idx(ei, is64, (long long)ne + e);
        if (s >= 0 && s < n && d >= 0 && d < n) {
            int p = atomicAdd(&g_cur[d], 1);
            g_col[p] = s;
            g_w[p]   = g_dinv[s] * g_dinv[d];
        }
    }
}

// ------- aggregation (no bias/relu): Out[i] = sum norm_ij * X[j] + dinv_i^2 X[i]
// F = feature width (64 or 128). warp per node.
template <int F, int SRC, int DST>
__global__ void k_agg(const float* __restrict__ Xext, int n) {
    const float* X = (SRC == 0) ? Xext : (SRC == 1 ? g_buf1 : g_buf2);
    float* O       = (DST == 1) ? g_buf1 : g_buf2;
    int lane = threadIdx.x & 31, warp = threadIdx.x >> 5;
    int i = blockIdx.x * 8 + warp;
    if (i >= n) return;
    int e0 = g_off[i], e1 = g_off[i + 1];
    float di = g_dinv[i];
    float sw = di * di;

    if (F == 64) {
        float2 acc = make_float2(0.f, 0.f);
        for (int e = e0; e < e1; e++) {
            int s = g_col[e];
            float wv = g_w[e];
            float2 hv = ((const float2*)(X + (size_t)s * 64))[lane];
            acc.x = fmaf(wv, hv.x, acc.x);
            acc.y = fmaf(wv, hv.y, acc.y);
        }
        float2 hs = ((const float2*)(X + (size_t)i * 64))[lane];
        acc.x = fmaf(sw, hs.x, acc.x);
        acc.y = fmaf(sw, hs.y, acc.y);
        ((float2*)(O + (size_t)i * 64))[lane] = acc;
    } else {
        float4 acc = make_float4(0.f, 0.f, 0.f, 0.f);
        for (int e = e0; e < e1; e++) {
            int s = g_col[e];
            float wv = g_w[e];
            float4 hv = ((const float4*)(X + (size_t)s * 128))[lane];
            acc.x = fmaf(wv, hv.x, acc.x);
            acc.y = fmaf(wv, hv.y, acc.y);
            acc.z = fmaf(wv, hv.z, acc.z);
            acc.w = fmaf(wv, hv.w, acc.w);
        }
        float4 hs = ((const float4*)(X + (size_t)i * 128))[lane];
        acc.x = fmaf(sw, hs.x, acc.x);
        acc.y = fmaf(sw, hs.y, acc.y);
        acc.z = fmaf(sw, hs.z, acc.z);
        acc.w = fmaf(sw, hs.w, acc.w);
        ((float4*)(O + (size_t)i * 128))[lane] = acc;
    }
}

// ------- GEMM + bias + relu: O[n,128] = relu(X[n,K] @ W[K,128] + b) ----------
// FFMA2 (f32x2) version: block = 128 rows (64 row-pairs), 8 warps.
// warp w handles rows 16w..16w+15 (pairs 8w..8w+7), all 128 cols (4 per lane).
// Accumulators are f32x2 {row_even, row_odd}.
template <int K, int SRC, int DST>
__global__ void k_gemm(const float* __restrict__ W, const float* __restrict__ bias, int n) {
    constexpr int CH = 32;
    __shared__ __align__(16) float  Wc[CH * 128];   // 16KB: K-chunk of W
    __shared__ __align__(16) float2 Xp[64 * CH];    // 16KB: 64 row-pairs x CH k
    const float* X = (SRC == 1) ? g_buf1 : g_buf2;
    float* O       = (DST == 1) ? g_buf1 : g_buf2;

    int tid = threadIdx.x, lane = tid & 31, warp = tid >> 5;
    int rb = blockIdx.x * 128;
    int pairbase = warp * 8;

    unsigned long long acc[8][4];
#pragma unroll
    for (int p = 0; p < 8; p++)
#pragma unroll
        for (int c = 0; c < 4; c++) acc[p][c] = 0ull;

    for (int c0 = 0; c0 < K; c0 += CH) {
        __syncthreads();
        // stage W chunk: CH*128 floats = 1024 float4
        {
            const float4* Wg4 = (const float4*)(W + c0 * 128);
            float4* Wc4 = (float4*)Wc;
#pragma unroll
            for (int i = 0; i < 4; i++) Wc4[tid + 256 * i] = Wg4[tid + 256 * i];
        }
        // stage X pairs: warp loads its 8 pairs, lane = k index
#pragma unroll
        for (int pp = 0; pp < 8; pp++) {
            int p = warp * 8 + pp;
            int r0 = rb + 2 * p;
            float v0 = (r0 < n)     ? X[(size_t)r0 * K + c0 + lane]       : 0.f;
            float v1 = (r0 + 1 < n) ? X[(size_t)(r0 + 1) * K + c0 + lane] : 0.f;
            Xp[p * CH + lane] = make_float2(v0, v1);
        }
        __syncthreads();

#pragma unroll 8
        for (int k = 0; k < CH; k++) {
            float4 wv = *(const float4*)&Wc[k * 128 + 4 * lane];
            unsigned long long w0 = pack2(wv.x, wv.x);
            unsigned long long w1 = pack2(wv.y, wv.y);
            unsigned long long w2 = pack2(wv.z, wv.z);
            unsigned long long w3 = pack2(wv.w, wv.w);
#pragma unroll
            for (int p = 0; p < 8; p++) {
                unsigned long long xp = *(const unsigned long long*)&Xp[(pairbase + p) * CH + k];
                acc[p][0] = ffma2(xp, w0, acc[p][0]);
                acc[p][1] = ffma2(xp, w1, acc[p][1]);
                acc[p][2] = ffma2(xp, w2, acc[p][2]);
                acc[p][3] = ffma2(xp, w3, acc[p][3]);
            }
        }
    }

    // epilogue: bias + relu, float4 stores
    float4 bv = *(const float4*)&bias[4 * lane];
#pragma unroll
    for (int p = 0; p < 8; p++) {
        float2 u0 = unpack2(acc[p][0]);
        float2 u1 = unpack2(acc[p][1]);
        float2 u2 = unpack2(acc[p][2]);
        float2 u3 = unpack2(acc[p][3]);
        int r0 = rb + 2 * (pairbase + p);
        float4 oe = make_float4(fmaxf(u0.x + bv.x, 0.f), fmaxf(u1.x + bv.y, 0.f),
                                fmaxf(u2.x + bv.z, 0.f), fmaxf(u3.x + bv.w, 0.f));
        float4 oo = make_float4(fmaxf(u0.y + bv.x, 0.f), fmaxf(u1.y + bv.y, 0.f),
                                fmaxf(u2.y + bv.z, 0.f), fmaxf(u3.y + bv.w, 0.f));
        if (r0 < n)     ((float4*)(O + (size_t)r0 * 128))[lane] = oe;
        if (r0 + 1 < n) ((float4*)(O + (size_t)(r0 + 1) * 128))[lane] = oo;
    }
}

// ---------------- head: out = log_softmax(H @ Wl + bl) -----------------------
__global__ void k_final(const float* __restrict__ Wl, const float* __restrict__ bl,
                        float* __restrict__ out, int n) {
    __shared__ __align__(16) float Wt[10 * 128];  // transposed: [j][k]
    __shared__ float bls[10];
    int tid = threadIdx.x;
    for (int idx = tid; idx < 1280; idx += 256) {
        int k = idx / 10, j = idx - 10 * k;
        Wt[j * 128 + k] = Wl[idx];
    }
    if (tid < 10) bls[tid] = bl[tid];
    __syncthreads();

    int lane = tid & 31, warp = tid >> 5;
    int i = blockIdx.x * 8 + warp;
    if (i >= n) return;
    float4 hv = ((const float4*)(g_buf2 + (size_t)i * HID))[lane];
    float lg[10];
#pragma unroll
    for (int j = 0; j < 10; j++) {
        float4 wv = ((const float4*)(Wt + j * 128))[lane];
        float p = hv.x * wv.x + hv.y * wv.y + hv.z * wv.z + hv.w * wv.w;
#pragma unroll
        for (int o = 16; o; o >>= 1) p += __shfl_xor_sync(0xffffffffu, p, o);
        lg[j] = p + bls[j];
    }
    float m = lg[0];
#pragma unroll
    for (int j = 1; j < 10; j++) m = fmaxf(m, lg[j]);
    float s = 0.f;
#pragma unroll
    for (int j = 0; j < 10; j++) s += expf(lg[j] - m);
    float lse = m + logf(s);
    if (lane < 10) out[(size_t)i * 10 + lane] = lg[lane] - lse;
}

// ---------------- launch -----------------------------------------------------
extern "C" void kernel_launch(void* const* d_in, const int* in_sizes, int n_in,
                              void* d_out, int out_size) {
    const float* x  = (const float*)d_in[0];
    const void*  ei = d_in[1];
    const float* W1 = (const float*)d_in[2];
    const float* b1 = (const float*)d_in[3];
    const float* W2 = (const float*)d_in[4];
    const float* b2 = (const float*)d_in[5];
    const float* Wl = (const float*)d_in[6];
    const float* bl = (const float*)d_in[7];
    float* out = (float*)d_out;

    int N = in_sizes[0] / 64;
    int E = in_sizes[1] / 2;

    // --- detect edge_index dtype, build normalized CSR ---
    k_detect<<<1, 32>>>((const int*)ei, 2 * E >= 2048 ? 2048 : 2 * E);
    k_zero_cnt<<<ceil_div(N, 256), 256>>>(N);
    k_hist<<<ceil_div(E, 256), 256>>>(ei, E, N);
    int nb = ceil_div(N, 2048);
    k_scan1<<<nb, 256>>>(N);
    k_scan2<<<1, 32>>>(nb);
    k_scan3<<<ceil_div(N, 256), 256>>>(N, E);
    k_fill<<<ceil_div(E, 256), 256>>>(ei, E, N);

    // --- layer 1 (agg-first; A(XW)= (AX)W): agg x (64) -> buf1; gemm+bias+relu -> buf2
    k_agg<64, 0, 1><<<ceil_div(N, 8), 256>>>(x, N);
    k_gemm<64, 1, 2><<<ceil_div(N, 128), 256>>>(W1, b1, N);

    // --- layer 2: agg buf2 (128) -> buf1; gemm+bias+relu -> buf2
    k_agg<128, 2, 1><<<ceil_div(N, 8), 256>>>(nullptr, N);
    k_gemm<128, 1, 2><<<ceil_div(N, 128), 256>>>(W2, b2, N);

    // --- head + log_softmax ---
    k_final<<<ceil_div(N, 8), 256>>>(Wl, bl, out, N);
}